// round 5
// baseline (speedup 1.0000x reference)
#include <cuda_runtime.h>
#include <cstdint>

#define NMAX   100000
#define EMAX   600000
#define HDIM   128
#define BCMAX  384

// ---------------- static scratch (no allocations allowed) ----------------
__device__ float g_x     [NMAX * HDIM];     // node features
__device__ float g_Y     [NMAX * 256];      // [Y1 | Y2] per node
__device__ float g_xin   [NMAX * 64];       // packed encoder input (padded 48->64)
__device__ float g_Wcomb [128 * 256];       // [Wu1+A | B]
__device__ float g_A     [128 * 128];       // Wm_i @ Wu2 (for deg==0 fixup)
__device__ float g_cvec  [128];             // b_m @ Wu2
__device__ float g_Wenc  [64 * 128];        // padded encoder weight
__device__ float g_pooled[BCMAX * HDIM];
__device__ float g_pr    [BCMAX * HDIM];    // pooled_scaled @ Wu3
__device__ int   g_rowptr[NMAX + 1];
__device__ int   g_rowfill[NMAX];
__device__ int   g_deg   [NMAX];
__device__ int   g_csr   [EMAX];
__device__ int   g_ccount[BCMAX];
__device__ int   g_coff  [BCMAX + 1];
__device__ int   g_cfill [BCMAX];
__device__ int   g_cnodes[NMAX];
__device__ int   g_bsum  [64];
__device__ int   g_bsumex[64];
__device__ int   g_srcA  [EMAX];
__device__ int   g_dstA  [EMAX];
__device__ int   g_ccA   [NMAX];
__device__ int   g_flag  [2];

// ---------------- dtype detection + index conversion ----------------
// int64 little-endian values in [0, N) have every odd int32 word == 0.
__global__ void k_detect(const int* __restrict__ e32, const int* __restrict__ c32,
                         int* flag) {
    int t = threadIdx.x;  // 32 threads
    int ok_e = 1, ok_c = 1;
    for (int i = t; i < 256; i += 32) {
        ok_e &= (e32[2 * i + 1] == 0);
        ok_c &= (c32[2 * i + 1] == 0);
    }
    ok_e = __all_sync(0xffffffffu, ok_e);
    ok_c = __all_sync(0xffffffffu, ok_c);
    if (t == 0) { flag[0] = ok_e; flag[1] = ok_c; }
}

__global__ void k_convert(const void* __restrict__ e, const void* __restrict__ cc,
                          int* __restrict__ srcA, int* __restrict__ dstA,
                          int* __restrict__ ccA, const int* __restrict__ flag,
                          int E, int n) {
    int i = blockIdx.x * blockDim.x + threadIdx.x;
    int f0 = flag[0], f1 = flag[1];
    if (i < E) {
        int s, d;
        if (f0) {
            const long long* e64 = (const long long*)e;
            s = (int)e64[i]; d = (int)e64[(size_t)E + i];
        } else {
            const int* e32 = (const int*)e;
            s = e32[i]; d = e32[E + i];
        }
        if ((unsigned)s >= (unsigned)n) s = 0;
        if ((unsigned)d >= (unsigned)n) d = 0;
        srcA[i] = s; dstA[i] = d;
    }
    if (i < n) {
        int c = f1 ? (int)((const long long*)cc)[i] : ((const int*)cc)[i];
        if ((unsigned)c >= (unsigned)BCMAX) c = 0;
        ccA[i] = c;
    }
}

// ---------------- small utility kernels ----------------
__global__ void k_zero(int* deg, int* ccount, int n, int bc) {
    int i = blockIdx.x * blockDim.x + threadIdx.x;
    if (i < n)  deg[i] = 0;
    if (i < bc) ccount[i] = 0;
}

__global__ void k_hist(const int* __restrict__ dstA, const int* __restrict__ ccA,
                       int* deg, int* ccount, int E, int n) {
    int i = blockIdx.x * blockDim.x + threadIdx.x;
    if (i < E) atomicAdd(&deg[dstA[i]], 1);
    if (i < n) atomicAdd(&ccount[ccA[i]], 1);
}

// exclusive scan, 2-level: per-block (4096 elems) scan + block sums
__global__ void k_scan_blocks(const int* __restrict__ in, int* __restrict__ out,
                              int* __restrict__ bsum, int n) {
    __shared__ int sm[1024];
    int t = threadIdx.x;
    int base = blockIdx.x * 4096 + t * 4;
    int v0 = (base + 0 < n) ? in[base + 0] : 0;
    int v1 = (base + 1 < n) ? in[base + 1] : 0;
    int v2 = (base + 2 < n) ? in[base + 2] : 0;
    int v3 = (base + 3 < n) ? in[base + 3] : 0;
    int tot = v0 + v1 + v2 + v3;
    sm[t] = tot; __syncthreads();
    for (int off = 1; off < 1024; off <<= 1) {
        int add = (t >= off) ? sm[t - off] : 0;
        __syncthreads();
        sm[t] += add;
        __syncthreads();
    }
    if (t == 1023) bsum[blockIdx.x] = sm[1023];
    int run = sm[t] - tot;
    if (base + 0 < n) out[base + 0] = run; run += v0;
    if (base + 1 < n) out[base + 1] = run; run += v1;
    if (base + 2 < n) out[base + 2] = run; run += v2;
    if (base + 3 < n) out[base + 3] = run;
}

__global__ void k_scan_small(const int* __restrict__ in, int* __restrict__ out,
                             int n, int writeTotal) {
    __shared__ int sm[1024];
    int t = threadIdx.x;
    int v = (t < n) ? in[t] : 0;
    sm[t] = v; __syncthreads();
    for (int off = 1; off < 1024; off <<= 1) {
        int add = (t >= off) ? sm[t - off] : 0;
        __syncthreads();
        sm[t] += add;
        __syncthreads();
    }
    if (t < n) out[t] = sm[t] - v;
    if (writeTotal && t == 1023) out[n] = sm[1023];
}

__global__ void k_addoff(int* rowptr, const int* bsumex, int n, int total) {
    int i = blockIdx.x * blockDim.x + threadIdx.x;
    if (i < n) rowptr[i] += bsumex[i >> 12];
    if (i == 0) rowptr[n] = total;
}

__global__ void k_fill(int* rowfill, const int* rowptr, int* cfill, const int* coff,
                       int n, int bc) {
    int i = blockIdx.x * blockDim.x + threadIdx.x;
    if (i < n)  rowfill[i] = rowptr[i];
    if (i < bc) cfill[i]   = coff[i];
}

__global__ void k_scatter(const int* __restrict__ srcA, const int* __restrict__ dstA,
                          const int* __restrict__ ccA,
                          int* rowfill, int* csr, int* cfill, int* cnodes, int E, int n) {
    int i = blockIdx.x * blockDim.x + threadIdx.x;
    if (i < E) {
        int pos = atomicAdd(&rowfill[dstA[i]], 1);
        if ((unsigned)pos < (unsigned)EMAX) csr[pos] = srcA[i];
    }
    if (i < n) {
        int pos = atomicAdd(&cfill[ccA[i]], 1);
        if ((unsigned)pos < (unsigned)NMAX) cnodes[pos] = i;
    }
}

// ---------------- weight folding ----------------
// Wcomb[k][0:128]  = Wu1[k][:] + (Wm_i @ Wu2)[k][:]
// Wcomb[k][128:256]= (Wm_j @ Wu2)[k][:]
__global__ void k_fold(const float* __restrict__ W_m, const float* __restrict__ W_u,
                       float* __restrict__ Wcomb, float* __restrict__ A) {
    int k = blockIdx.x;      // 0..127
    int t = threadIdx.x;     // 0..255
    __shared__ float wi[128], wj[128];
    if (t < 128) {
        wi[t] = W_m[k * 128 + t];
        wj[t] = W_m[(128 + k) * 128 + t];
    }
    __syncthreads();
    if (t < 128) {
        float acc = 0.f;
        #pragma unroll 8
        for (int q = 0; q < 128; q++) acc += wi[q] * W_u[(128 + q) * 128 + t];
        A[k * 128 + t] = acc;
        Wcomb[k * 256 + t] = W_u[k * 128 + t] + acc;
    } else {
        int j = t - 128;
        float acc = 0.f;
        #pragma unroll 8
        for (int q = 0; q < 128; q++) acc += wj[q] * W_u[(128 + q) * 128 + j];
        Wcomb[k * 256 + 128 + j] = acc;
    }
}

__global__ void k_cvec(const float* __restrict__ b_m, const float* __restrict__ W_u,
                       float* __restrict__ cvec) {
    int j = threadIdx.x;
    float acc = 0.f;
    #pragma unroll 8
    for (int k = 0; k < 128; k++) acc += b_m[k] * W_u[(128 + k) * 128 + j];
    cvec[j] = acc;
}

__global__ void k_wenc(const float* __restrict__ W_enc, float* __restrict__ Wenc) {
    int k = blockIdx.x, h = threadIdx.x;
    Wenc[k * 128 + h] = (k < 48) ? W_enc[k * 128 + h] : 0.f;
}

__global__ void k_pack(const float* __restrict__ cf, const float* __restrict__ slf,
                       const float* __restrict__ z, float* __restrict__ xin, int n) {
    int i = blockIdx.x * blockDim.x + threadIdx.x;
    if (i >= n * 64) return;
    int nd = i >> 6, c = i & 63;
    float v;
    if (c < 15)       v = cf[nd * 15 + c];
    else if (c == 15) v = slf[nd];
    else if (c < 48)  v = z[nd * 32 + (c - 16)];
    else              v = 0.f;
    xin[i] = v;
}

// ---------------- tf32 GEMM: C[M,NC] = X[M,K] @ W[K,NC] (+bias) ----------------
__device__ __forceinline__ float to_tf32(float x) {
    float r; asm("cvt.rna.tf32.f32 %0, %1;" : "=f"(r) : "f"(x)); return r;
}

template<int K, int NC, bool BIAS>
__global__ __launch_bounds__(256) void k_gemm(
    const float* __restrict__ X, const float* __restrict__ W,
    const float* __restrict__ bias, float* __restrict__ C, int M) {
    __shared__ float As[128 * 36];
    __shared__ float Bs[32 * 132];
    const int tid = threadIdx.x;
    const int lane = tid & 31, wid = tid >> 5;
    const int wm = wid & 3, wn = wid >> 2;
    const int gid = lane >> 2, tig = lane & 3;
    const int row0 = blockIdx.x * 128;
    const int col0 = blockIdx.y * 128;
    float acc[2][8][4];
    #pragma unroll
    for (int mi = 0; mi < 2; mi++)
        #pragma unroll
        for (int ni = 0; ni < 8; ni++)
            #pragma unroll
            for (int q = 0; q < 4; q++) acc[mi][ni][q] = 0.f;

    for (int kb = 0; kb < K; kb += 32) {
        #pragma unroll
        for (int i = 0; i < 4; i++) {
            int f = tid + i * 256;
            int r = f >> 3, c4 = (f & 7) * 4;
            int grow = row0 + r;
            float4 v = make_float4(0.f, 0.f, 0.f, 0.f);
            if (grow < M) v = *(const float4*)(X + (size_t)grow * K + kb + c4);
            float* dst = &As[r * 36 + c4];
            dst[0] = to_tf32(v.x); dst[1] = to_tf32(v.y);
            dst[2] = to_tf32(v.z); dst[3] = to_tf32(v.w);
        }
        #pragma unroll
        for (int i = 0; i < 4; i++) {
            int f = tid + i * 256;
            int k = f >> 5, n4 = (f & 31) * 4;
            float4 v = *(const float4*)(W + (size_t)(kb + k) * NC + col0 + n4);
            float* dst = &Bs[k * 132 + n4];
            dst[0] = to_tf32(v.x); dst[1] = to_tf32(v.y);
            dst[2] = to_tf32(v.z); dst[3] = to_tf32(v.w);
        }
        __syncthreads();
        #pragma unroll
        for (int kk = 0; kk < 4; kk++) {
            const int kc = kk * 8;
            unsigned a[2][4];
            #pragma unroll
            for (int mi = 0; mi < 2; mi++) {
                int rb = wm * 32 + mi * 16;
                a[mi][0] = __float_as_uint(As[(rb + gid    ) * 36 + kc + tig]);
                a[mi][1] = __float_as_uint(As[(rb + gid + 8) * 36 + kc + tig]);
                a[mi][2] = __float_as_uint(As[(rb + gid    ) * 36 + kc + tig + 4]);
                a[mi][3] = __float_as_uint(As[(rb + gid + 8) * 36 + kc + tig + 4]);
            }
            unsigned b[8][2];
            #pragma unroll
            for (int ni = 0; ni < 8; ni++) {
                int cb = wn * 64 + ni * 8 + gid;
                b[ni][0] = __float_as_uint(Bs[(kc + tig    ) * 132 + cb]);
                b[ni][1] = __float_as_uint(Bs[(kc + tig + 4) * 132 + cb]);
            }
            #pragma unroll
            for (int mi = 0; mi < 2; mi++)
                #pragma unroll
                for (int ni = 0; ni < 8; ni++)
                    asm volatile(
                        "mma.sync.aligned.m16n8k8.row.col.f32.tf32.tf32.f32 "
                        "{%0,%1,%2,%3}, {%4,%5,%6,%7}, {%8,%9}, {%0,%1,%2,%3};\n"
                        : "+f"(acc[mi][ni][0]), "+f"(acc[mi][ni][1]),
                          "+f"(acc[mi][ni][2]), "+f"(acc[mi][ni][3])
                        : "r"(a[mi][0]), "r"(a[mi][1]), "r"(a[mi][2]), "r"(a[mi][3]),
                          "r"(b[ni][0]), "r"(b[ni][1]));
        }
        __syncthreads();
    }
    #pragma unroll
    for (int mi = 0; mi < 2; mi++) {
        int r0 = row0 + wm * 32 + mi * 16 + gid;
        #pragma unroll
        for (int ni = 0; ni < 8; ni++) {
            int c = col0 + wn * 64 + ni * 8 + tig * 2;
            float b0 = 0.f, b1 = 0.f;
            if (BIAS) { b0 = bias[c]; b1 = bias[c + 1]; }
            if (r0 < M) {
                float2 o = make_float2(acc[mi][ni][0] + b0, acc[mi][ni][1] + b1);
                *(float2*)(C + (size_t)r0 * NC + c) = o;
            }
            if (r0 + 8 < M) {
                float2 o = make_float2(acc[mi][ni][2] + b0, acc[mi][ni][3] + b1);
                *(float2*)(C + (size_t)(r0 + 8) * NC + c) = o;
            }
        }
    }
}

// ---------------- cluster pooling ----------------
__global__ void k_pool(const float* __restrict__ x, const int* __restrict__ coff,
                       const int* __restrict__ cnodes, const float* __restrict__ tr,
                       float* __restrict__ pooled) {
    int c = blockIdx.x;
    int t = threadIdx.x;            // 256
    int col = t & 127, sub = t >> 7;
    int beg = coff[c], end = coff[c + 1];
    float acc = 0.f;
    for (int i = beg + sub; i < end; i += 2) {
        int nd = __ldg(&cnodes[i]);
        acc += __ldg(&x[(size_t)nd * 128 + col]);
    }
    __shared__ float red[256];
    red[t] = acc; __syncthreads();
    if (t < 128) {
        int cnt = end - beg;
        float scale = tr[c] / (float)(cnt > 1 ? cnt : 1);
        pooled[c * 128 + t] = (red[t] + red[t + 128]) * scale;
    }
}

__global__ void k_pr(const float* __restrict__ pooled, const float* __restrict__ W_u,
                     float* __restrict__ pr) {
    int c = blockIdx.x, t = threadIdx.x;  // 128
    __shared__ float prow[128];
    prow[t] = pooled[c * 128 + t];
    __syncthreads();
    float acc = 0.f;
    #pragma unroll 8
    for (int k = 0; k < 128; k++) acc += prow[k] * W_u[(256 + k) * 128 + t];
    pr[c * 128 + t] = acc;
}

// ---------------- fused edge aggregation + node update (warp per node) ----------------
__global__ void k_aggupd(const float* __restrict__ Y, const int* __restrict__ rowptr,
                         const int* __restrict__ csr, const float* __restrict__ pr,
                         const int* __restrict__ ccA, const float* __restrict__ cvec,
                         const float* __restrict__ b_u, const float* __restrict__ A,
                         const float* __restrict__ x_in, float* __restrict__ x_out, int n) {
    int w = (blockIdx.x * blockDim.x + threadIdx.x) >> 5;
    int lane = threadIdx.x & 31;
    if (w >= n) return;
    int beg = rowptr[w], end = rowptr[w + 1];
    float4 s = make_float4(0.f, 0.f, 0.f, 0.f);
    float4 s2 = make_float4(0.f, 0.f, 0.f, 0.f);
    for (int base = beg; base < end; base += 32) {
        int m = min(32, end - base);
        int sv = (lane < m) ? __ldg(&csr[base + lane]) : 0;
        int j = 0;
        for (; j + 2 <= m; j += 2) {
            int srcA_ = __shfl_sync(0xffffffffu, sv, j);
            int srcB_ = __shfl_sync(0xffffffffu, sv, j + 1);
            float4 va = __ldg((const float4*)(Y + (size_t)srcA_ * 256 + 128 + lane * 4));
            float4 vb = __ldg((const float4*)(Y + (size_t)srcB_ * 256 + 128 + lane * 4));
            s.x += va.x; s.y += va.y; s.z += va.z; s.w += va.w;
            s2.x += vb.x; s2.y += vb.y; s2.z += vb.z; s2.w += vb.w;
        }
        if (j < m) {
            int src = __shfl_sync(0xffffffffu, sv, j);
            float4 v = __ldg((const float4*)(Y + (size_t)src * 256 + 128 + lane * 4));
            s.x += v.x; s.y += v.y; s.z += v.z; s.w += v.w;
        }
    }
    s.x += s2.x; s.y += s2.y; s.z += s2.z; s.w += s2.w;
    int deg = end - beg;
    if (deg > 0) {
        float4 cv = *(const float4*)(cvec + lane * 4);
        float inv = 1.0f / (float)deg;
        s.x = s.x * inv + cv.x; s.y = s.y * inv + cv.y;
        s.z = s.z * inv + cv.z; s.w = s.w * inv + cv.w;
    } else {
        // fixup: subtract x@A so that Y1 (= x@(Wu1+A)) collapses to x@Wu1
        float4 t = make_float4(0.f, 0.f, 0.f, 0.f);
        const float* xr = x_in + (size_t)w * 128;
        for (int k = 0; k < 128; k++) {
            float xv = xr[k];
            float4 a = __ldg((const float4*)(A + k * 128 + lane * 4));
            t.x += xv * a.x; t.y += xv * a.y; t.z += xv * a.z; t.w += xv * a.w;
        }
        s.x = -t.x; s.y = -t.y; s.z = -t.z; s.w = -t.w;
    }
    int c = ccA[w];
    float4 y1 = __ldg((const float4*)(Y + (size_t)w * 256 + lane * 4));
    float4 p  = __ldg((const float4*)(pr + c * 128 + lane * 4));
    float4 bu = *(const float4*)(b_u + lane * 4);
    float4 xi = __ldg((const float4*)(x_in + (size_t)w * 128 + lane * 4));
    float u0 = y1.x + s.x + p.x + bu.x; u0 = (u0 > 0.f) ? u0 : 0.01f * u0;
    float u1 = y1.y + s.y + p.y + bu.y; u1 = (u1 > 0.f) ? u1 : 0.01f * u1;
    float u2 = y1.z + s.z + p.z + bu.z; u2 = (u2 > 0.f) ? u2 : 0.01f * u2;
    float u3 = y1.w + s.w + p.w + bu.w; u3 = (u3 > 0.f) ? u3 : 0.01f * u3;
    float4 o = make_float4(xi.x + u0, xi.y + u1, xi.z + u2, xi.w + u3);
    *(float4*)(x_out + (size_t)w * 128 + lane * 4) = o;
}

// ---------------- launch ----------------
extern "C" void kernel_launch(void* const* d_in, const int* in_sizes, int n_in,
                              void* d_out, int out_size) {
    const float* cf    = (const float*)d_in[0];
    const float* slf   = (const float*)d_in[1];
    const float* z     = (const float*)d_in[2];
    const float* tr    = (const float*)d_in[3];
    const float* W_enc = (const float*)d_in[4];
    const float* b_enc = (const float*)d_in[5];
    const float* W_m   = (const float*)d_in[6];
    const float* b_m   = (const float*)d_in[7];
    const float* W_u   = (const float*)d_in[8];
    const float* b_u   = (const float*)d_in[9];
    const void*  e     = d_in[10];
    const void*  cc    = d_in[11];
    float* out = (float*)d_out;

    int n  = in_sizes[0] / 15;   // 100000
    int E  = in_sizes[10] / 2;   // 600000
    int bc = in_sizes[3];        // 384

    float *x, *Y, *xin, *Wcomb, *A, *cvec, *Wenc, *pooled, *pr;
    int *rowptr, *rowfill, *deg, *csr, *ccount, *coff, *cfill, *cnodes, *bsum, *bsumex;
    int *srcA, *dstA, *ccA, *flag;
    cudaGetSymbolAddress((void**)&x,      g_x);
    cudaGetSymbolAddress((void**)&Y,      g_Y);
    cudaGetSymbolAddress((void**)&xin,    g_xin);
    cudaGetSymbolAddress((void**)&Wcomb,  g_Wcomb);
    cudaGetSymbolAddress((void**)&A,      g_A);
    cudaGetSymbolAddress((void**)&cvec,   g_cvec);
    cudaGetSymbolAddress((void**)&Wenc,   g_Wenc);
    cudaGetSymbolAddress((void**)&pooled, g_pooled);
    cudaGetSymbolAddress((void**)&pr,     g_pr);
    cudaGetSymbolAddress((void**)&rowptr, g_rowptr);
    cudaGetSymbolAddress((void**)&rowfill,g_rowfill);
    cudaGetSymbolAddress((void**)&deg,    g_deg);
    cudaGetSymbolAddress((void**)&csr,    g_csr);
    cudaGetSymbolAddress((void**)&ccount, g_ccount);
    cudaGetSymbolAddress((void**)&coff,   g_coff);
    cudaGetSymbolAddress((void**)&cfill,  g_cfill);
    cudaGetSymbolAddress((void**)&cnodes, g_cnodes);
    cudaGetSymbolAddress((void**)&bsum,   g_bsum);
    cudaGetSymbolAddress((void**)&bsumex, g_bsumex);
    cudaGetSymbolAddress((void**)&srcA,   g_srcA);
    cudaGetSymbolAddress((void**)&dstA,   g_dstA);
    cudaGetSymbolAddress((void**)&ccA,    g_ccA);
    cudaGetSymbolAddress((void**)&flag,   g_flag);

    // ---- dtype detect + convert indices to int32 ----
    k_detect<<<1, 32>>>((const int*)e, (const int*)cc, flag);
    k_convert<<<(E + 255) / 256, 256>>>(e, cc, srcA, dstA, ccA, flag, E, n);

    // ---- CSR build (edges by dst, nodes by cluster) ----
    k_zero<<<(n + 255) / 256, 256>>>(deg, ccount, n, bc);
    k_hist<<<(E + 255) / 256, 256>>>(dstA, ccA, deg, ccount, E, n);
    int nb = (n + 4095) / 4096;
    k_scan_blocks<<<nb, 1024>>>(deg, rowptr, bsum, n);
    k_scan_small<<<1, 1024>>>(bsum, bsumex, nb, 0);
    k_addoff<<<(n + 1023) / 1024, 1024>>>(rowptr, bsumex, n, E);
    k_scan_small<<<1, 1024>>>(ccount, coff, bc, 1);
    k_fill<<<(n + 255) / 256, 256>>>(rowfill, rowptr, cfill, coff, n, bc);
    k_scatter<<<(E + 255) / 256, 256>>>(srcA, dstA, ccA, rowfill, csr, cfill, cnodes, E, n);

    // ---- weight folds ----
    k_fold<<<128, 256>>>(W_m, W_u, Wcomb, A);
    k_cvec<<<1, 128>>>(b_m, W_u, cvec);
    k_wenc<<<64, 128>>>(W_enc, Wenc);

    // ---- encoder ----
    k_pack<<<((size_t)n * 64 + 255) / 256, 256>>>(cf, slf, z, xin, n);
    int bm = (n + 127) / 128;
    k_gemm<64, 128, true><<<dim3(bm, 1), 256>>>(xin, Wenc, b_enc, x, n);

    // ---- 3 GNN layers ----
    for (int l = 0; l < 3; l++) {
        k_gemm<128, 256, false><<<dim3(bm, 2), 256>>>(x, Wcomb, nullptr, Y, n);
        k_pool<<<bc, 256>>>(x, coff, cnodes, tr, pooled);
        k_pr<<<bc, 128>>>(pooled, W_u, pr);
        float* xo = (l == 2) ? out : x;
        k_aggupd<<<((size_t)n * 32 + 255) / 256, 256>>>(Y, rowptr, csr, pr, ccA, cvec,
                                                        b_u, A, x, xo, n);
    }
}